// round 12
// baseline (speedup 1.0000x reference)
#include <cuda_runtime.h>
#include <cuda_bf16.h>
#include <cstdint>

#define TPB        256
#define SPLIT      8
#define MAX_B      1024
#define MAX_NT     2048
#define STAGE_BYTES 16384
#define STAGE_F4   (STAGE_BYTES / 16)

// cross-kernel scratch (allocation-free). g_key/g_cnt zero at load and
// self-reset by the finisher -> deterministic across graph replays.
__device__ unsigned long long g_key[MAX_B];
__device__ int                g_cnt[MAX_B];
__device__ int                g_list[MAX_B];
__device__ int                g_nrej;

__device__ __forceinline__ uint32_t smem_u32(const void* p) {
    uint32_t a;
    asm("{ .reg .u64 t; cvta.to.shared.u64 t, %1; cvt.u32.u64 %0, t; }"
        : "=r"(a) : "l"(p));
    return a;
}
__device__ __forceinline__ void mbar_init(uint32_t mbar) {
    asm volatile("mbarrier.init.shared.b64 [%0], 1;" :: "r"(mbar) : "memory");
}
__device__ __forceinline__ void mbar_expect(uint32_t mbar, uint32_t bytes) {
    asm volatile("mbarrier.arrive.expect_tx.shared.b64 _, [%0], %1;"
                 :: "r"(mbar), "r"(bytes) : "memory");
}
__device__ __forceinline__ void mbar_wait(uint32_t mbar, uint32_t parity) {
    asm volatile(
        "{\n\t.reg .pred P;\n\t"
        "W_%=:\n\t"
        "mbarrier.try_wait.parity.acquire.cta.shared::cta.b64 P, [%0], %1, 0x989680;\n\t"
        "@P bra.uni D_%=;\n\t"
        "bra.uni W_%=;\n\t"
        "D_%=:\n\t}"
        :: "r"(mbar), "r"(parity) : "memory");
}
__device__ __forceinline__ void tma_bulk_1d(uint32_t dst, const void* src,
                                            uint32_t bytes, uint32_t mbar) {
    asm volatile(
        "cp.async.bulk.shared::cta.global.mbarrier::complete_tx::bytes "
        "[%0], [%1], %2, [%3];"
        :: "r"(dst), "l"(src), "r"(bytes), "r"(mbar) : "memory");
}

// ---------- Kernel A: token-parallel gather + per-request scan --------------
__global__ void __launch_bounds__(512)
scan_compact(const float* __restrict__ draft_probs,
             const float* __restrict__ target_probs,
             const float* __restrict__ uniform_probs,
             const int*   __restrict__ draft_token_ids,
             const int*   __restrict__ cu,
             const int*   __restrict__ bonus,
             float*       __restrict__ out,
             int B, int NT, int V, int L)
{
    __shared__ int   sid[MAX_NT];
    __shared__ float stp[MAX_NT];
    __shared__ float sdp[MAX_NT];
    __shared__ float su [MAX_NT];
    __shared__ int   scu[MAX_B];
    __shared__ int   wcnt[16];

    const int tid = threadIdx.x;

    // round 1: cu and token ids (independent, concurrent)
    for (int r = tid; r < B; r += 512) scu[r] = __ldg(&cu[r]);
    for (int t = tid; t < NT; t += 512) sid[t] = __ldg(&draft_token_ids[t]);
    __syncthreads();

    // round 2: prob/uniform gathers, token-parallel (one latency round)
    for (int t = tid; t < NT; t += 512) {
        const int idv = sid[t];
        stp[t] = __ldg(&target_probs[(size_t)t * V + idv]);
        sdp[t] = __ldg(&draft_probs [(size_t)t * V + idv]);
        su [t] = __ldg(&uniform_probs[t]);
    }
    __syncthreads();

    // per-request scan (threads 0..B-1), faithful to reference
    const int r      = tid;
    const bool activ = (r < B);
    int start = 0, end = 0;
    if (activ) { start = (r == 0) ? 0 : scu[r - 1]; end = scu[r]; }
    const int nd  = end - start;
    const int lim = (nd < L) ? nd : L;

    float pi = 1.0f, U = 1.0f;
    int last = -1;
    for (int j = 0; j < lim; j++) {
        const int t = start + j;
        const float dpj = sdp[t];
        const float ratio = (dpj > 0.0f) ? (stp[t] / dpj) : 1.0f;
        pi = fminf(pi * ratio, 1.0f);
        U *= su[t];
        if ((dpj > 0.0f) && (pi >= U)) last = j;
    }

    const int rejected  = (activ && nd > 0 && last != nd - 1) ? 1 : 0;
    const int write_col = rejected ? (last + 1) : nd;

    if (activ) {
        float* orow = out + (size_t)r * (L + 1);
        for (int j = 0; j <= L; j++) {
            float v = -1.0f;
            if (j < L && j <= last) v = (float)sid[start + j];
            orow[j] = v;
        }
        if (!rejected) orow[write_col] = (float)__ldg(&bonus[r]);
    }

    int rec = start + last + 1;
    rec = (rec < 0) ? 0 : rec;
    rec = (rec > NT - 1) ? (NT - 1) : rec;

    // compaction (ballot + cross-warp prefix; deterministic order)
    const int warp = tid >> 5, lane = tid & 31;
    const unsigned ball = __ballot_sync(0xffffffffu, rejected);
    const int rank = __popc(ball & ((1u << lane) - 1));
    if (lane == 0) wcnt[warp] = __popc(ball);
    __syncthreads();
    int base = 0, total = 0;
    #pragma unroll
    for (int w = 0; w < 16; w++) {
        if (w < warp) base += wcnt[w];
        total += wcnt[w];
    }
    if (rejected)
        g_list[base + rank] = r | (write_col << 8) | (rec << 12);
    if (tid == 0) g_nrej = total;
}

// ---------- Kernel B: TMA-bulk double-buffered split argmax -----------------
__global__ void __launch_bounds__(TPB)
argmax_kernel(const float* __restrict__ target_probs,
              float* __restrict__ out, int V, int L)
{
    const int row = blockIdx.x / SPLIT;
    if (row >= g_nrej) return;
    const int s   = blockIdx.x % SPLIT;
    const int tid = threadIdx.x;

    const int e   = g_list[row];               // broadcast L2 read
    const int r   = e & 0xff;
    const int pos = (e >> 8) & 0xf;
    const int rec = e >> 12;

    const int chunk = (((V + SPLIT - 1) / SPLIT) + 3) & ~3;   // 4-aligned floats
    const int nact  = (V + chunk - 1) / chunk;
    if (s >= nact) return;
    const int beg = s * chunk;
    const int fin = min(V, beg + chunk);

    const float* rowp  = target_probs + (size_t)rec * V;
    const int n4beg = beg >> 2;
    const int n4end = fin >> 2;
    const int total_bytes = (n4end - n4beg) * 16;

    __shared__ __align__(128) char sbuf[2][STAGE_BYTES];
    __shared__ __align__(8) unsigned long long sbar[2];

    float  best  = -1.0f;                      // probs >= 0
    int    bbase = -1;
    float4 bv    = make_float4(0.f, 0.f, 0.f, 0.f);

    if (total_bytes > 0) {
        const char* gsrc = (const char*)(rowp + (n4beg << 2));
        const int nst = (total_bytes + STAGE_BYTES - 1) / STAGE_BYTES;
        const uint32_t bar0 = smem_u32(&sbar[0]);
        const uint32_t bar1 = smem_u32(&sbar[1]);
        const uint32_t buf0 = smem_u32(&sbuf[0][0]);
        const uint32_t buf1 = smem_u32(&sbuf[1][0]);

        if (tid == 0) { mbar_init(bar0); mbar_init(bar1); }
        __syncthreads();
        if (tid == 0) {
            const uint32_t b0 = (uint32_t)min(STAGE_BYTES, total_bytes);
            mbar_expect(bar0, b0);
            tma_bulk_1d(buf0, gsrc, b0, bar0);
        }

        for (int st = 0; st < nst; st++) {
            const int sbytes = min(STAGE_BYTES, total_bytes - st * STAGE_BYTES);
            // issue next stage into the other buffer (safe: its reduce done)
            if (tid == 0 && st + 1 < nst) {
                const uint32_t nb =
                    (uint32_t)min(STAGE_BYTES, total_bytes - (st + 1) * STAGE_BYTES);
                const uint32_t nbar = ((st + 1) & 1) ? bar1 : bar0;
                const uint32_t nbuf = ((st + 1) & 1) ? buf1 : buf0;
                mbar_expect(nbar, nb);
                tma_bulk_1d(nbuf, gsrc + (size_t)(st + 1) * STAGE_BYTES, nb, nbar);
            }
            mbar_wait((st & 1) ? bar1 : bar0, (st >> 1) & 1);

            const int nf4 = sbytes >> 4;
            const float4* sb = (const float4*)sbuf[st & 1];
            #pragma unroll 4
            for (int i = tid; i < nf4; i += TPB) {
                const float4 v = sb[i];
                const int gi4 = n4beg + st * STAGE_F4 + i;
                const float m = fmaxf(fmaxf(v.x, v.y), fmaxf(v.z, v.w));
                if (m > best) { best = m; bbase = gi4 << 2; bv = v; }
            }
            __syncthreads();   // buffer st&1 free for reuse at stage st+2
        }
    }

    int bidx = 0x7fffffff;
    if (bbase >= 0) {
        bidx = bbase + ((bv.x == best) ? 0 : (bv.y == best) ? 1
                      : (bv.z == best) ? 2 : 3);
    }
    // scalar tail (V not divisible by 4; only last split can hit this)
    {
        const int t0 = n4end << 2;
        if (tid < fin - t0) {
            const float vv = __ldg(&rowp[t0 + tid]);
            const int   ii = t0 + tid;
            if (vv > best || (vv == best && ii < bidx)) { best = vv; bidx = ii; }
        }
    }

    // warp reduce (min-index tie-break -> global first occurrence)
    #pragma unroll
    for (int off = 16; off > 0; off >>= 1) {
        const float ov = __shfl_down_sync(0xffffffffu, best, off);
        const int   oi = __shfl_down_sync(0xffffffffu, bidx, off);
        if (ov > best || (ov == best && oi < bidx)) { best = ov; bidx = oi; }
    }

    __shared__ float wv[TPB / 32];
    __shared__ int   wi[TPB / 32];
    const int warp = tid >> 5, lane = tid & 31;
    if (lane == 0) { wv[warp] = best; wi[warp] = bidx; }
    __syncthreads();

    if (tid == 0) {
        #pragma unroll
        for (int w = 1; w < TPB / 32; w++) {
            if (wv[w] > best || (wv[w] == best && wi[w] < bidx)) {
                best = wv[w]; bidx = wi[w];
            }
        }
        // pack: prob bits (monotone for >=0 floats) | ~index (ties -> min idx)
        const unsigned long long key =
            ((unsigned long long)__float_as_uint(best) << 32) |
            (unsigned long long)(~(unsigned)bidx);
        atomicMax(&g_key[r], key);
        __threadfence();
        const int old = atomicAdd(&g_cnt[r], 1);
        if (old == nact - 1) {                       // last finisher
            const unsigned long long k = atomicMax(&g_key[r], 0ULL);
            const int idx = (int)(~(unsigned)(k & 0xffffffffULL));
            out[(size_t)r * (L + 1) + pos] = (float)idx;
            g_key[r] = 0ULL;                         // self-reset for replay
            g_cnt[r] = 0;
        }
    }
}

extern "C" void kernel_launch(void* const* d_in, const int* in_sizes, int n_in,
                              void* d_out, int out_size) {
    const float* draft_probs     = (const float*)d_in[0];
    const float* target_probs    = (const float*)d_in[1];
    const float* uniform_probs   = (const float*)d_in[2];
    const int*   draft_token_ids = (const int*)  d_in[3];
    const int*   cu              = (const int*)  d_in[4];
    const int*   bonus           = (const int*)  d_in[5];
    float*       out             = (float*)d_out;

    const int NT = in_sizes[3];
    const int B  = in_sizes[4];
    const int V  = in_sizes[0] / NT;
    const int L  = out_size / B - 1;

    scan_compact<<<1, 512>>>(draft_probs, target_probs, uniform_probs,
                             draft_token_ids, cu, bonus, out, B, NT, V, L);
    argmax_kernel<<<B * SPLIT, TPB>>>(target_probs, out, V, L);
}